// round 13
// baseline (speedup 1.0000x reference)
#include <cuda_runtime.h>

#define NODES 336
#define NPC   8192
#define NUMCASE 2048
#define MIU_F 1.9e-05f
#define ALPHA_F 0.10471975511965977f   // 6*pi/180
#define QCOEF_F 73830.75f              // 0.5*1.225*ACOUSTIC^2
#define FULL 0xffffffffu

// Block=96: 2048 CTAs x 96thr = 13.8 CTAs/SM -> ALL CTAs resident, single wave.
// One MUFU per node: tau = MIU*(f.T)*rsqrt(|T|^2 * |delta|^2).
// Thread t owns nodes t+96k, k=0..3 (k=3 only for t<48).
__global__ __launch_bounds__(96, 14) void dyn_kernel(
    const float* __restrict__ coords,
    const float* __restrict__ fields,
    const float* __restrict__ design,
    float2* __restrict__ out)
{
    const int c = blockIdx.x;
    const int base = c * NPC;
    const int t = threadIdx.x;

    __shared__ float2 s_n0[NODES];
    __shared__ float  s_tau[NODES];
    __shared__ float  s_red[3][4];

    float2 n0[4], n1[4];
    float f1u[4], f1v[4], pt[4];
    float d3 = 0.f, d4 = 0.f;

    const float2* cf2 = (const float2*)coords;

    // ---- Phase 0: front-batched loads (up to 24 independent LDGs/thread) ----
    #pragma unroll
    for (int k = 0; k < 4; k++) {
        int j = t + k * 96;
        bool valid = (k < 3) || (t < NODES - 288);
        if (valid) {
            n0[k] = cf2[base + j];
            n1[k] = cf2[base + NODES + j];
            // f1[:, :, 2:] only: float2 at row offset +8 bytes
            float2 f1zw = *(const float2*)(fields + 4 * (base + NODES + j) + 2);
            f1u[k] = f1zw.x;
            f1v[k] = f1zw.y;
            pt[k]  = fields[4 * (base + j)];          // f0[:, :, 0]
            d3 += design[5 * (base + j) + 3];
            d4 += design[5 * (base + j) + 4];
            s_n0[j] = n0[k];
        }
    }
    __syncthreads();

    // ---- Phase 1: tau once per node, ONE fused MUFU ----
    float Tx[4], Ty[4];
    #pragma unroll
    for (int k = 0; k < 4; k++) {
        int j = t + k * 96;
        bool valid = (k < 3) || (t < NODES - 288);
        if (valid) {
            int jp = (j + 1 == NODES) ? 0 : j + 1;
            float2 np = s_n0[jp];
            float tx = np.x - n0[k].x, ty = np.y - n0[k].y;
            Tx[k] = tx; Ty[k] = ty;
            float tn2 = tx * tx + ty * ty;
            float dx = n1[k].x - n0[k].x, dy = n1[k].y - n0[k].y;
            float dl2 = dx * dx + dy * dy;
            s_tau[j] = MIU_F * (f1u[k] * tx + f1v[k] * ty) * rsqrtf(tn2 * dl2);
        }
    }
    __syncthreads();

    // ---- Phase 2: forces (no MUFU) ----
    float Fx = 0.f, Fy = 0.f;
    #pragma unroll
    for (int k = 0; k < 4; k++) {
        int j = t + k * 96;
        bool valid = (k < 3) || (t < NODES - 288);
        if (valid) {
            int jp = (j + 1 == NODES) ? 0 : j + 1;
            float tau_ave = 0.5f * (s_tau[j] + s_tau[jp]);
            // -Px = -pt*T.y ; -Py = +pt*T.x ; +50*tau_ave*T
            Fx += -pt[k] * Ty[k] + 50.f * tau_ave * Tx[k];
            Fy +=  pt[k] * Tx[k] + 50.f * tau_ave * Ty[k];
        }
    }

    // ---- Block reduction over 3 warps ----
    #pragma unroll
    for (int off = 16; off; off >>= 1) {
        Fx += __shfl_down_sync(FULL, Fx, off);
        Fy += __shfl_down_sync(FULL, Fy, off);
        d3 += __shfl_down_sync(FULL, d3, off);
        d4 += __shfl_down_sync(FULL, d4, off);
    }
    int warp = t >> 5, lane = t & 31;
    if (lane == 0) {
        s_red[warp][0] = Fx;
        s_red[warp][1] = Fy;
        s_red[warp][2] = d3;
        s_red[warp][3] = d4;
    }
    __syncthreads();

    if (t == 0) {
        float fx = s_red[0][0] + s_red[1][0] + s_red[2][0];
        float fy = s_red[0][1] + s_red[1][1] + s_red[2][1];
        float s3 = s_red[0][2] + s_red[1][2] + s_red[2][2];
        float s4 = s_red[0][3] + s_red[1][3] + s_red[2][3];
        float Ma = s3 * (0.3f / (float)NODES) + 0.3f;
        float af = s4 * (ALPHA_F / (float)NODES);
        float ca = cosf(af), sa = sinf(af);
        float Fxn = fx * ca + fy * sa;
        float Fyn = fy * ca - Fxn * sa;   // reference uses Fx_new here (literal)
        float q = QCOEF_F * Ma * Ma;
        out[c] = make_float2(Fxn / q, Fyn / q);
    }
}

extern "C" void kernel_launch(void* const* d_in, const int* in_sizes, int n_in,
                              void* d_out, int out_size) {
    // metadata order: batch(int32), coords(f32), fields(f32), design(f32), num_case, nodes_num
    const float* coords = (const float*)d_in[1];
    const float* fields = (const float*)d_in[2];
    const float* design = (const float*)d_in[3];
    float2* out = (float2*)d_out;
    dyn_kernel<<<NUMCASE, 96>>>(coords, fields, design, out);
}

// round 14
// speedup vs baseline: 1.0037x; 1.0037x over previous
#include <cuda_runtime.h>

#define NODES 336
#define NPC   8192
#define NUMCASE 2048
#define MIU_F 1.9e-05f
#define ALPHA_F 0.10471975511965977f   // 6*pi/180
#define QCOEF_F 73830.75f              // 0.5*1.225*ACOUSTIC^2
#define FULL 0xffffffffu

// Index-shift identity: sum_j tau_ave[j]*T[j] = sum_j tau[j]*(T[j]+T[j-1])/2,
// so tau never round-trips through smem -> ONE barrier, one MUFU per node.
// Block=96: all 2048 CTAs resident (13.8/SM), single wave.
__global__ __launch_bounds__(96, 14) void dyn_kernel(
    const float* __restrict__ coords,
    const float* __restrict__ fields,
    const float* __restrict__ design,
    float2* __restrict__ out)
{
    const int c = blockIdx.x;
    const int base = c * NPC;
    const int t = threadIdx.x;

    __shared__ float2 s_n0[NODES];
    __shared__ float  s_red[3][4];

    float2 n0[4], n1[4];
    float f1u[4], f1v[4], pt[4];
    float d3 = 0.f, d4 = 0.f;

    const float2* cf2 = (const float2*)coords;

    // ---- Phase 0: front-batched loads ----
    #pragma unroll
    for (int k = 0; k < 4; k++) {
        int j = t + k * 96;
        bool valid = (k < 3) || (t < NODES - 288);
        if (valid) {
            n0[k] = cf2[base + j];
            n1[k] = cf2[base + NODES + j];
            float2 f1zw = *(const float2*)(fields + 4 * (base + NODES + j) + 2);
            f1u[k] = f1zw.x;
            f1v[k] = f1zw.y;
            pt[k]  = fields[4 * (base + j)];          // f0[:, :, 0]
            d3 += design[5 * (base + j) + 3];
            d4 += design[5 * (base + j) + 4];
            s_n0[j] = n0[k];
        }
    }
    __syncthreads();

    // ---- Phase 1: tau once per node, accumulate with (T[j]+T[j-1])/2 ----
    float Fx = 0.f, Fy = 0.f;
    #pragma unroll
    for (int k = 0; k < 4; k++) {
        int j = t + k * 96;
        bool valid = (k < 3) || (t < NODES - 288);
        if (valid) {
            int jp = (j + 1 == NODES) ? 0 : j + 1;
            int jm = (j == 0) ? NODES - 1 : j - 1;
            float2 np = s_n0[jp];
            float2 nm = s_n0[jm];
            float tx  = np.x - n0[k].x, ty  = np.y - n0[k].y;   // T[j]
            float txm = n0[k].x - nm.x, tym = n0[k].y - nm.y;   // T[j-1]
            float tn2 = tx * tx + ty * ty;
            float dx = n1[k].x - n0[k].x, dy = n1[k].y - n0[k].y;
            float dl2 = dx * dx + dy * dy;
            float tau = MIU_F * (f1u[k] * tx + f1v[k] * ty) * rsqrtf(tn2 * dl2);
            float t50 = 50.f * tau;
            // pressure: -pt*T.y, +pt*T.x ; friction: 50*tau*(T[j]+T[j-1])/2
            Fx += -pt[k] * ty + t50 * (0.5f * (tx + txm));
            Fy +=  pt[k] * tx + t50 * (0.5f * (ty + tym));
        }
    }

    // ---- Block reduction over 3 warps ----
    #pragma unroll
    for (int off = 16; off; off >>= 1) {
        Fx += __shfl_down_sync(FULL, Fx, off);
        Fy += __shfl_down_sync(FULL, Fy, off);
        d3 += __shfl_down_sync(FULL, d3, off);
        d4 += __shfl_down_sync(FULL, d4, off);
    }
    int warp = t >> 5, lane = t & 31;
    if (lane == 0) {
        s_red[warp][0] = Fx;
        s_red[warp][1] = Fy;
        s_red[warp][2] = d3;
        s_red[warp][3] = d4;
    }
    __syncthreads();

    if (t == 0) {
        float fx = s_red[0][0] + s_red[1][0] + s_red[2][0];
        float fy = s_red[0][1] + s_red[1][1] + s_red[2][1];
        float s3 = s_red[0][2] + s_red[1][2] + s_red[2][2];
        float s4 = s_red[0][3] + s_red[1][3] + s_red[2][3];
        float Ma = s3 * (0.3f / (float)NODES) + 0.3f;
        float af = s4 * (ALPHA_F / (float)NODES);
        float ca = cosf(af), sa = sinf(af);
        float Fxn = fx * ca + fy * sa;
        float Fyn = fy * ca - Fxn * sa;   // reference uses Fx_new here (literal)
        float q = QCOEF_F * Ma * Ma;
        out[c] = make_float2(Fxn / q, Fyn / q);
    }
}

extern "C" void kernel_launch(void* const* d_in, const int* in_sizes, int n_in,
                              void* d_out, int out_size) {
    // metadata order: batch(int32), coords(f32), fields(f32), design(f32), num_case, nodes_num
    const float* coords = (const float*)d_in[1];
    const float* fields = (const float*)d_in[2];
    const float* design = (const float*)d_in[3];
    float2* out = (float2*)d_out;
    dyn_kernel<<<NUMCASE, 96>>>(coords, fields, design, out);
}